// round 2
// baseline (speedup 1.0000x reference)
#include <cuda_runtime.h>
#include <math.h>

#define NMAT   64          // B*H = 4*16 independent matrices
#define SLEN   2048        // rows per matrix
#define DDIM   128         // cols per matrix
#define RANK   64
#define KCH    8           // split-K chunks for Gram
#define SROWS  (SLEN/KCH)  // 256 rows per chunk
#define MAXSWEEPS 9

// scratch (static device globals — no allocations)
__device__ float g_gpart[(size_t)NMAT * KCH * DDIM * DDIM]; // 32 MB Gram partials
__device__ float g_P[(size_t)NMAT * DDIM * DDIM];           // 4 MB projectors

// ---------------------------------------------------------------------------
// Kernel 1: partial Gram  G_m += X_chunk^T X_chunk   (fp32)
// grid (KCH, NMAT), 256 threads, 8x8 register tile per thread
// ---------------------------------------------------------------------------
__global__ __launch_bounds__(256) void gram_partial_kernel(const float* __restrict__ X)
{
    __shared__ float Xs[32 * 128];
    const int m  = blockIdx.y;
    const int kc = blockIdx.x;
    const float* Xm = X + (size_t)m * SLEN * DDIM;
    const int tid = threadIdx.x;
    const int tx = tid & 15, ty = tid >> 4;

    float acc[8][8];
#pragma unroll
    for (int i = 0; i < 8; i++)
#pragma unroll
        for (int j = 0; j < 8; j++) acc[i][j] = 0.f;

    const int s0 = kc * SROWS;
    for (int it = 0; it < SROWS / 32; ++it) {
#pragma unroll
        for (int k = 0; k < 4; k++) {
            int idx = tid + k * 256;            // float4 index within 32x128 tile
            int row = idx >> 5, c4 = idx & 31;
            float4 v = *(const float4*)(Xm + (size_t)(s0 + it * 32 + row) * DDIM + c4 * 4);
            *(float4*)(Xs + row * 128 + c4 * 4) = v;
        }
        __syncthreads();
#pragma unroll
        for (int s = 0; s < 32; s++) {
            float a[8], b[8];
            *(float4*)(a)     = *(const float4*)(Xs + s * 128 + ty * 8);
            *(float4*)(a + 4) = *(const float4*)(Xs + s * 128 + ty * 8 + 4);
            *(float4*)(b)     = *(const float4*)(Xs + s * 128 + tx * 8);
            *(float4*)(b + 4) = *(const float4*)(Xs + s * 128 + tx * 8 + 4);
#pragma unroll
            for (int i = 0; i < 8; i++)
#pragma unroll
                for (int j = 0; j < 8; j++) acc[i][j] += a[i] * b[j];
        }
        __syncthreads();
    }

    float* out = g_gpart + ((size_t)m * KCH + kc) * DDIM * DDIM;
#pragma unroll
    for (int i = 0; i < 8; i++) {
        *(float4*)(out + (ty * 8 + i) * 128 + tx * 8)     =
            make_float4(acc[i][0], acc[i][1], acc[i][2], acc[i][3]);
        *(float4*)(out + (ty * 8 + i) * 128 + tx * 8 + 4) =
            make_float4(acc[i][4], acc[i][5], acc[i][6], acc[i][7]);
    }
}

// ---------------------------------------------------------------------------
// Kernel 2: one-sided Jacobi on G (128x128) per matrix; emits projector P.
// 64 blocks x 1024 threads. B column-major in dynamic SMEM (64 KB).
// 64 disjoint pairs per round, 16 threads per pair (8 floats each),
// round-robin tournament; early exit when a sweep performs no rotation.
// ---------------------------------------------------------------------------
__global__ __launch_bounds__(1024) void jacobi_kernel()
{
    extern __shared__ float B[];     // [128 cols][128 rows], col-major
    __shared__ float nrm2[128];
    __shared__ float w[128];
    __shared__ int any_rot;

    const int m   = blockIdx.x;
    const int tid = threadIdx.x;

    // load + reduce split-K partials into SMEM (G symmetric: row==col major)
    const float* gp = g_gpart + (size_t)m * KCH * DDIM * DDIM;
#pragma unroll
    for (int k = 0; k < 4; k++) {
        int i4 = tid + k * 1024;
        float4 s = make_float4(0.f, 0.f, 0.f, 0.f);
#pragma unroll
        for (int p = 0; p < KCH; p++) {
            float4 v = *(const float4*)(gp + (size_t)p * DDIM * DDIM + i4 * 4);
            s.x += v.x; s.y += v.y; s.z += v.z; s.w += v.w;
        }
        *(float4*)(B + i4 * 4) = s;
    }
    __syncthreads();

    const int pairIdx = tid >> 4;   // 0..63
    const int sub     = tid & 15;   // 16 threads per pair, 8 floats each

    for (int sweep = 0; sweep < MAXSWEEPS; ++sweep) {
        // exact column norms (fixes incremental drift each sweep)
        {
            int col = tid >> 3, part = tid & 7;            // 8 threads / col
            const float* bc = B + col * 128 + part * 16;   // 16 contiguous floats
            float ss = 0.f;
#pragma unroll
            for (int k = 0; k < 4; k++) {
                float4 v = *(const float4*)(bc + k * 4);
                ss += v.x * v.x + v.y * v.y + v.z * v.z + v.w * v.w;
            }
            ss += __shfl_xor_sync(0xffffffffu, ss, 1);
            ss += __shfl_xor_sync(0xffffffffu, ss, 2);
            ss += __shfl_xor_sync(0xffffffffu, ss, 4);
            if (part == 0) nrm2[col] = ss;
            if (tid == 0) any_rot = 0;
        }
        __syncthreads();

        for (int r = 0; r < 127; r++) {
            // round-robin tournament pairing (player 127 fixed)
            int p, q;
            if (pairIdx == 0) { p = 127; q = r; }
            else {
                p = r + pairIdx;        if (p >= 127) p -= 127;
                q = r + 127 - pairIdx;  if (q >= 127) q -= 127;
            }
            float* bp = B + p * 128 + sub * 8;
            float* bq = B + q * 128 + sub * 8;
            float4 p4[2], q4[2];
            p4[0] = *(const float4*)(bp);
            p4[1] = *(const float4*)(bp + 4);
            q4[0] = *(const float4*)(bq);
            q4[1] = *(const float4*)(bq + 4);

            float g = 0.f;
#pragma unroll
            for (int k = 0; k < 2; k++)
                g += p4[k].x * q4[k].x + p4[k].y * q4[k].y +
                     p4[k].z * q4[k].z + p4[k].w * q4[k].w;
            g += __shfl_xor_sync(0xffffffffu, g, 1);
            g += __shfl_xor_sync(0xffffffffu, g, 2);
            g += __shfl_xor_sync(0xffffffffu, g, 4);
            g += __shfl_xor_sync(0xffffffffu, g, 8);

            float al = nrm2[p], be = nrm2[q];
            if (g * g > 4e-13f * al * be) {   // uniform within the 16-lane group
                float zeta = (be - al) / (2.f * g);
                float t = 1.f / (fabsf(zeta) + sqrtf(1.f + zeta * zeta));
                t = (zeta < 0.f) ? -t : t;
                float c  = rsqrtf(1.f + t * t);
                float sn = c * t;
#pragma unroll
                for (int k = 0; k < 2; k++) {
                    float4 np, nq;
                    np.x = c * p4[k].x - sn * q4[k].x;  nq.x = sn * p4[k].x + c * q4[k].x;
                    np.y = c * p4[k].y - sn * q4[k].y;  nq.y = sn * p4[k].y + c * q4[k].y;
                    np.z = c * p4[k].z - sn * q4[k].z;  nq.z = sn * p4[k].z + c * q4[k].z;
                    np.w = c * p4[k].w - sn * q4[k].w;  nq.w = sn * p4[k].w + c * q4[k].w;
                    *(float4*)((k == 0) ? bp : bp + 4) = np;
                    *(float4*)((k == 0) ? bq : bq + 4) = nq;
                }
                if (sub == 0) {
                    nrm2[p] = al - t * g;
                    nrm2[q] = be + t * g;
                    any_rot = 1;
                }
            }
            __syncthreads();
        }

        // early exit: last round's __syncthreads makes any_rot coherent here.
        int rot = any_rot;
        __syncthreads();          // protect against thread 0 resetting it early
        if (!rot) break;
    }

    // final exact norms (||b_k||^2 = lambda_k^2)
    {
        int col = tid >> 3, part = tid & 7;
        const float* bc = B + col * 128 + part * 16;
        float ss = 0.f;
#pragma unroll
        for (int k = 0; k < 4; k++) {
            float4 v = *(const float4*)(bc + k * 4);
            ss += v.x * v.x + v.y * v.y + v.z * v.z + v.w * v.w;
        }
        ss += __shfl_xor_sync(0xffffffffu, ss, 1);
        ss += __shfl_xor_sync(0xffffffffu, ss, 2);
        ss += __shfl_xor_sync(0xffffffffu, ss, 4);
        if (part == 0) nrm2[col] = ss;
    }
    __syncthreads();

    // select top-RANK columns by norm; weight = 1/||b||^2 so P = sum w b b^T
    if (tid < 128) {
        float nj = nrm2[tid];
        int rk = 0;
        for (int i = 0; i < 128; i++) {
            float ni = nrm2[i];
            rk += (ni > nj) || (ni == nj && i < tid);
        }
        w[tid] = (rk < RANK) ? 1.f / nj : 0.f;
    }
    __syncthreads();

    // P[r][c] = sum_j w_j * B[j][r] * B[j][c]   (1024 threads: 32x32 grid, 4x4 tile)
    {
        int tx = tid & 31, ty = tid >> 5;
        int c0 = tx * 4, r0 = ty * 4;
        float acc[4][4];
#pragma unroll
        for (int i = 0; i < 4; i++)
#pragma unroll
            for (int l = 0; l < 4; l++) acc[i][l] = 0.f;

        for (int j = 0; j < 128; j++) {
            float wj = w[j];
            if (wj == 0.f) continue;          // uniform branch: halves work
            const float* bj = B + j * 128;
            float4 br4 = *(const float4*)(bj + r0);
            float4 bc4 = *(const float4*)(bj + c0);
            bc4.x *= wj; bc4.y *= wj; bc4.z *= wj; bc4.w *= wj;
            float br[4] = {br4.x, br4.y, br4.z, br4.w};
#pragma unroll
            for (int i = 0; i < 4; i++) {
                acc[i][0] += br[i] * bc4.x;
                acc[i][1] += br[i] * bc4.y;
                acc[i][2] += br[i] * bc4.z;
                acc[i][3] += br[i] * bc4.w;
            }
        }
        float* Pm = g_P + (size_t)m * DDIM * DDIM;
#pragma unroll
        for (int i = 0; i < 4; i++)
            *(float4*)(Pm + (r0 + i) * 128 + c0) =
                make_float4(acc[i][0], acc[i][1], acc[i][2], acc[i][3]);
    }
}

// ---------------------------------------------------------------------------
// Kernel 3: out = X @ P  (fp32). grid (32, NMAT), 256 threads, 64-row tiles.
// ---------------------------------------------------------------------------
__global__ __launch_bounds__(256) void recon_kernel(const float* __restrict__ X,
                                                    float* __restrict__ out)
{
    extern __shared__ float sm[];
    float* Ps = sm;          // 128*128
    float* Xs = sm + 16384;  // 64*128
    const int m  = blockIdx.y;
    const int s0 = blockIdx.x * 64;
    const int tid = threadIdx.x;

    const float* Pm = g_P + (size_t)m * DDIM * DDIM;
#pragma unroll
    for (int k = 0; k < 16; k++) {
        int i4 = tid + k * 256;
        *(float4*)(Ps + i4 * 4) = *(const float4*)(Pm + i4 * 4);
    }
    const float* Xm = X + (size_t)m * SLEN * DDIM + (size_t)s0 * DDIM;
#pragma unroll
    for (int k = 0; k < 8; k++) {
        int i4 = tid + k * 256;
        *(float4*)(Xs + i4 * 4) = *(const float4*)(Xm + i4 * 4);
    }
    __syncthreads();

    const int tx = tid & 31, ty = tid >> 5;   // 32 x 8
    const int c0 = tx * 4, r0 = ty * 8;
    float acc[8][4];
#pragma unroll
    for (int i = 0; i < 8; i++)
#pragma unroll
        for (int l = 0; l < 4; l++) acc[i][l] = 0.f;

#pragma unroll 4
    for (int k = 0; k < 128; k++) {
        float4 b4 = *(const float4*)(Ps + k * 128 + c0);
#pragma unroll
        for (int i = 0; i < 8; i++) {
            float a = Xs[(r0 + i) * 128 + k];   // warp-uniform -> broadcast
            acc[i][0] += a * b4.x;
            acc[i][1] += a * b4.y;
            acc[i][2] += a * b4.z;
            acc[i][3] += a * b4.w;
        }
    }

    float* outm = out + (size_t)m * SLEN * DDIM + (size_t)s0 * DDIM;
#pragma unroll
    for (int i = 0; i < 8; i++)
        *(float4*)(outm + (r0 + i) * 128 + c0) =
            make_float4(acc[i][0], acc[i][1], acc[i][2], acc[i][3]);
}

// ---------------------------------------------------------------------------
extern "C" void kernel_launch(void* const* d_in, const int* in_sizes, int n_in,
                              void* d_out, int out_size)
{
    const float* X = (const float*)d_in[0];
    float* out = (float*)d_out;

    cudaFuncSetAttribute(jacobi_kernel, cudaFuncAttributeMaxDynamicSharedMemorySize,
                         128 * 128 * 4);
    cudaFuncSetAttribute(recon_kernel, cudaFuncAttributeMaxDynamicSharedMemorySize,
                         (16384 + 8192) * 4);

    gram_partial_kernel<<<dim3(KCH, NMAT), 256>>>(X);
    jacobi_kernel<<<NMAT, 1024, 128 * 128 * 4>>>();
    recon_kernel<<<dim3(SLEN / 64, NMAT), 256, (16384 + 8192) * 4>>>(X, out);
}

// round 3
// speedup vs baseline: 1.0946x; 1.0946x over previous
#include <cuda_runtime.h>
#include <math.h>

#define NMAT   64          // B*H = 4*16 independent matrices
#define SLEN   2048        // rows per matrix
#define DDIM   128         // cols per matrix
#define RANK   64
#define KCH    8           // split-K chunks for Gram
#define SROWS  (SLEN/KCH)  // 256 rows per chunk
#define MAXSWEEPS 8
#define JTH    4e-13f      // rotation skip threshold (g^2 > JTH*a*b)

typedef unsigned long long u64;

// scratch (static device globals — no allocations)
__device__ float g_gpart[(size_t)NMAT * KCH * DDIM * DDIM]; // 32 MB Gram partials
__device__ float g_P[(size_t)NMAT * DDIM * DDIM];           // 4 MB projectors

// ---- packed f32x2 helpers (PTX-only; ptxas won't auto-fuse) ------------------
__device__ __forceinline__ u64 pk2(float a, float b) {
    u64 r; asm("mov.b64 %0, {%1, %2};" : "=l"(r) : "f"(a), "f"(b)); return r;
}
__device__ __forceinline__ void upk2(u64 v, float& a, float& b) {
    asm("mov.b64 {%0, %1}, %2;" : "=f"(a), "=f"(b) : "l"(v));
}
__device__ __forceinline__ u64 fma2(u64 a, u64 b, u64 c) {
    u64 d; asm("fma.rn.f32x2 %0, %1, %2, %3;" : "=l"(d) : "l"(a), "l"(b), "l"(c)); return d;
}
__device__ __forceinline__ u64 mul2(u64 a, u64 b) {
    u64 d; asm("mul.rn.f32x2 %0, %1, %2;" : "=l"(d) : "l"(a), "l"(b)); return d;
}
__device__ __forceinline__ float warp_red(float v) {
    v += __shfl_xor_sync(0xffffffffu, v, 16);
    v += __shfl_xor_sync(0xffffffffu, v, 8);
    v += __shfl_xor_sync(0xffffffffu, v, 4);
    v += __shfl_xor_sync(0xffffffffu, v, 2);
    v += __shfl_xor_sync(0xffffffffu, v, 1);
    return v;
}

// ---------------------------------------------------------------------------
// Kernel 1: partial Gram  G_m += X_chunk^T X_chunk   (fp32)
// ---------------------------------------------------------------------------
__global__ __launch_bounds__(256) void gram_partial_kernel(const float* __restrict__ X)
{
    __shared__ float Xs[32 * 128];
    const int m  = blockIdx.y;
    const int kc = blockIdx.x;
    const float* Xm = X + (size_t)m * SLEN * DDIM;
    const int tid = threadIdx.x;
    const int tx = tid & 15, ty = tid >> 4;

    float acc[8][8];
#pragma unroll
    for (int i = 0; i < 8; i++)
#pragma unroll
        for (int j = 0; j < 8; j++) acc[i][j] = 0.f;

    const int s0 = kc * SROWS;
    for (int it = 0; it < SROWS / 32; ++it) {
#pragma unroll
        for (int k = 0; k < 4; k++) {
            int idx = tid + k * 256;
            int row = idx >> 5, c4 = idx & 31;
            float4 v = *(const float4*)(Xm + (size_t)(s0 + it * 32 + row) * DDIM + c4 * 4);
            *(float4*)(Xs + row * 128 + c4 * 4) = v;
        }
        __syncthreads();
#pragma unroll
        for (int s = 0; s < 32; s++) {
            float a[8], b[8];
            *(float4*)(a)     = *(const float4*)(Xs + s * 128 + ty * 8);
            *(float4*)(a + 4) = *(const float4*)(Xs + s * 128 + ty * 8 + 4);
            *(float4*)(b)     = *(const float4*)(Xs + s * 128 + tx * 8);
            *(float4*)(b + 4) = *(const float4*)(Xs + s * 128 + tx * 8 + 4);
#pragma unroll
            for (int i = 0; i < 8; i++)
#pragma unroll
                for (int j = 0; j < 8; j++) acc[i][j] += a[i] * b[j];
        }
        __syncthreads();
    }

    float* out = g_gpart + ((size_t)m * KCH + kc) * DDIM * DDIM;
#pragma unroll
    for (int i = 0; i < 8; i++) {
        *(float4*)(out + (ty * 8 + i) * 128 + tx * 8)     =
            make_float4(acc[i][0], acc[i][1], acc[i][2], acc[i][3]);
        *(float4*)(out + (ty * 8 + i) * 128 + tx * 8 + 4) =
            make_float4(acc[i][4], acc[i][5], acc[i][6], acc[i][7]);
    }
}

// ---------------------------------------------------------------------------
// Kernel 2: register-resident one-sided Jacobi (tournament / circle method).
// 64 blocks x 512 threads (16 warps). Each warp owns 4 pairs = 8 columns in
// registers (4 floats per lane per column, packed as 2x f32x2). Per round only
// 2 columns per warp cross a warp boundary via double-buffered SMEM staging.
// One __syncthreads per round.
// ---------------------------------------------------------------------------
__global__ __launch_bounds__(512) void jacobi_kernel()
{
    extern __shared__ float S[];            // 64KB: staging during rounds, B at end
    __shared__ float nrm2[128];
    __shared__ float w[128];
    __shared__ float nstgT[2][16], nstgB[2][16];
    __shared__ int any_rot;

    const int m    = blockIdx.x;
    const int tid  = threadIdx.x;
    const int wid  = tid >> 5;
    const int lane = tid & 31;

    // ---- reduce split-K partials into S (G symmetric: row-major == col-major)
    const float* gp = g_gpart + (size_t)m * KCH * DDIM * DDIM;
#pragma unroll
    for (int k = 0; k < 8; k++) {
        int i4 = tid + k * 512;
        float4 s = make_float4(0.f, 0.f, 0.f, 0.f);
#pragma unroll
        for (int p = 0; p < KCH; p++) {
            float4 v = *(const float4*)(gp + (size_t)p * DDIM * DDIM + i4 * 4);
            s.x += v.x; s.y += v.y; s.z += v.z; s.w += v.w;
        }
        *(float4*)(S + i4 * 4) = s;
    }
    __syncthreads();

    // ---- load this warp's 8 columns into registers
    // top[k] = column 4*wid+k, bot[k] = column 64+4*wid+k
    u64 tlo[4], thi[4], blo[4], bhi[4];
    float ntv[4], nbv[4];
#pragma unroll
    for (int k = 0; k < 4; k++) {
        float4 v = *(const float4*)(S + (4 * wid + k) * 128 + lane * 4);
        tlo[k] = pk2(v.x, v.y); thi[k] = pk2(v.z, v.w);
        v = *(const float4*)(S + (64 + 4 * wid + k) * 128 + lane * 4);
        blo[k] = pk2(v.x, v.y); bhi[k] = pk2(v.z, v.w);
    }
    __syncthreads();   // S now free for staging reuse

    for (int sweep = 0; sweep < MAXSWEEPS; ++sweep) {
        // exact norms (warp-local, no barrier needed)
#pragma unroll
        for (int k = 0; k < 4; k++) {
            u64 acc = mul2(tlo[k], tlo[k]); acc = fma2(thi[k], thi[k], acc);
            float a, b; upk2(acc, a, b); ntv[k] = warp_red(a + b);
            acc = mul2(blo[k], blo[k]); acc = fma2(bhi[k], bhi[k], acc);
            upk2(acc, a, b); nbv[k] = warp_red(a + b);
        }
        __syncthreads();
        if (tid == 0) any_rot = 0;
        __syncthreads();

#pragma unroll 1
        for (int r = 0; r < 127; r++) {
            const int par = r & 1;

            // dots for 4 pairs
            float g[4];
#pragma unroll
            for (int k = 0; k < 4; k++) {
                u64 acc = mul2(tlo[k], blo[k]); acc = fma2(thi[k], bhi[k], acc);
                float a, b; upk2(acc, a, b); g[k] = a + b;
            }
#pragma unroll
            for (int off = 16; off >= 1; off >>= 1) {
#pragma unroll
                for (int k = 0; k < 4; k++)
                    g[k] += __shfl_xor_sync(0xffffffffu, g[k], off);
            }

            // rotate (warp-uniform per pair)
#pragma unroll
            for (int k = 0; k < 4; k++) {
                float al = ntv[k], be = nbv[k], gg = g[k];
                if (gg * gg > JTH * al * be) {
                    float zeta = (be - al) / (2.f * gg);
                    float t = 1.f / (fabsf(zeta) + sqrtf(1.f + zeta * zeta));
                    t = (zeta < 0.f) ? -t : t;
                    float c  = rsqrtf(1.f + t * t);
                    float sn = c * t;
                    u64 c2 = pk2(c, c), s2 = pk2(sn, sn), ns2 = pk2(-sn, -sn);
                    u64 nt_lo = fma2(c2, tlo[k], mul2(ns2, blo[k]));
                    u64 nb_lo = fma2(s2, tlo[k], mul2(c2,  blo[k]));
                    u64 nt_hi = fma2(c2, thi[k], mul2(ns2, bhi[k]));
                    u64 nb_hi = fma2(s2, thi[k], mul2(c2,  bhi[k]));
                    tlo[k] = nt_lo; thi[k] = nt_hi;
                    blo[k] = nb_lo; bhi[k] = nb_hi;
                    ntv[k] = al - t * gg;
                    nbv[k] = be + t * gg;
                    if (lane == 0) any_rot = 1;
                }
            }

            // stage outgoing columns (post-rotation)
            // outgoing: top[3] -> warp wid+1 (all wid<15); bot[0] -> warp wid-1 (all wid>0)
            {
                float* stT = S + (par * 32 + wid) * 128;
                float* stB = S + (par * 32 + 16 + wid) * 128;
                if (wid < 15) {
                    *(u64*)(stT + lane * 4)     = tlo[3];
                    *(u64*)(stT + lane * 4 + 2) = thi[3];
                    if (lane == 0) nstgT[par][wid] = ntv[3];
                }
                if (wid > 0) {
                    *(u64*)(stB + lane * 4)     = blo[0];
                    *(u64*)(stB + lane * 4 + 2) = bhi[0];
                    if (lane == 0) nstgB[par][wid] = nbv[0];
                }
            }
            __syncthreads();

            // incoming + register shift (circle rotation, top[0] of warp0 fixed)
            u64 inTlo = 0, inThi = 0, inBlo = 0, inBhi = 0;
            float inNT = 0.f, inNB = 0.f;
            if (wid > 0) {
                const float* ld = S + (par * 32 + wid - 1) * 128;
                inTlo = *(const u64*)(ld + lane * 4);
                inThi = *(const u64*)(ld + lane * 4 + 2);
                inNT  = nstgT[par][wid - 1];
            }
            if (wid < 15) {
                const float* ld = S + (par * 32 + 16 + wid + 1) * 128;
                inBlo = *(const u64*)(ld + lane * 4);
                inBhi = *(const u64*)(ld + lane * 4 + 2);
                inNB  = nstgB[par][wid + 1];
            }

            if (wid == 0) {
                u64 b0lo = blo[0], b0hi = bhi[0]; float b0n = nbv[0];
                tlo[3] = tlo[2]; thi[3] = thi[2]; ntv[3] = ntv[2];
                tlo[2] = tlo[1]; thi[2] = thi[1]; ntv[2] = ntv[1];
                tlo[1] = b0lo;   thi[1] = b0hi;   ntv[1] = b0n;
                // top[0] fixed
                blo[0] = blo[1]; bhi[0] = bhi[1]; nbv[0] = nbv[1];
                blo[1] = blo[2]; bhi[1] = bhi[2]; nbv[1] = nbv[2];
                blo[2] = blo[3]; bhi[2] = bhi[3]; nbv[2] = nbv[3];
                blo[3] = inBlo;  bhi[3] = inBhi;  nbv[3] = inNB;
            } else if (wid == 15) {
                u64 t3lo = tlo[3], t3hi = thi[3]; float t3n = ntv[3];
                tlo[3] = tlo[2]; thi[3] = thi[2]; ntv[3] = ntv[2];
                tlo[2] = tlo[1]; thi[2] = thi[1]; ntv[2] = ntv[1];
                tlo[1] = tlo[0]; thi[1] = thi[0]; ntv[1] = ntv[0];
                tlo[0] = inTlo;  thi[0] = inThi;  ntv[0] = inNT;
                blo[0] = blo[1]; bhi[0] = bhi[1]; nbv[0] = nbv[1];
                blo[1] = blo[2]; bhi[1] = bhi[2]; nbv[1] = nbv[2];
                blo[2] = blo[3]; bhi[2] = bhi[3]; nbv[2] = nbv[3];
                blo[3] = t3lo;   bhi[3] = t3hi;   nbv[3] = t3n;
            } else {
                tlo[3] = tlo[2]; thi[3] = thi[2]; ntv[3] = ntv[2];
                tlo[2] = tlo[1]; thi[2] = thi[1]; ntv[2] = ntv[1];
                tlo[1] = tlo[0]; thi[1] = thi[0]; ntv[1] = ntv[0];
                tlo[0] = inTlo;  thi[0] = inThi;  ntv[0] = inNT;
                blo[0] = blo[1]; bhi[0] = bhi[1]; nbv[0] = nbv[1];
                blo[1] = blo[2]; bhi[1] = bhi[2]; nbv[1] = nbv[2];
                blo[2] = blo[3]; bhi[2] = bhi[3]; nbv[2] = nbv[3];
                blo[3] = inBlo;  bhi[3] = inBhi;  nbv[3] = inNB;
            }
        }

        int rot = any_rot;   // writes all precede round-126's barrier
        if (!rot) break;
    }

    // ---- dump columns + exact norms to SMEM
    __syncthreads();   // all staging reads done before overwriting S
#pragma unroll
    for (int k = 0; k < 4; k++) {
        float* dT = S + (4 * wid + k) * 128;
        float* dB = S + (64 + 4 * wid + k) * 128;
        *(u64*)(dT + lane * 4)     = tlo[k];
        *(u64*)(dT + lane * 4 + 2) = thi[k];
        *(u64*)(dB + lane * 4)     = blo[k];
        *(u64*)(dB + lane * 4 + 2) = bhi[k];

        u64 acc = mul2(tlo[k], tlo[k]); acc = fma2(thi[k], thi[k], acc);
        float a, b; upk2(acc, a, b); float nt = warp_red(a + b);
        acc = mul2(blo[k], blo[k]); acc = fma2(bhi[k], bhi[k], acc);
        upk2(acc, a, b); float nb = warp_red(a + b);
        if (lane == 0) { nrm2[4 * wid + k] = nt; nrm2[64 + 4 * wid + k] = nb; }
    }
    __syncthreads();

    // ---- select top-RANK by norm; weight = 1/||b||^2 so P = sum w b b^T
    if (tid < 128) {
        float nj = nrm2[tid];
        int rk = 0;
        for (int i = 0; i < 128; i++) {
            float ni = nrm2[i];
            rk += (ni > nj) || (ni == nj && i < tid);
        }
        w[tid] = (rk < RANK) ? 1.f / nj : 0.f;
    }
    __syncthreads();

    // ---- P[r][c] = sum_j w_j * B[j][r] * B[j][c]   (32x16 grid, 8x4 tile)
    {
        int tx = tid & 31, ty = tid >> 5;
        int c0 = tx * 4, r0 = ty * 8;
        float acc[8][4];
#pragma unroll
        for (int i = 0; i < 8; i++)
#pragma unroll
            for (int l = 0; l < 4; l++) acc[i][l] = 0.f;

        for (int j = 0; j < 128; j++) {
            float wj = w[j];
            if (wj == 0.f) continue;
            const float* bj = S + j * 128;
            float br[8];
            *(float4*)(br)     = *(const float4*)(bj + r0);
            *(float4*)(br + 4) = *(const float4*)(bj + r0 + 4);
            float4 bc4 = *(const float4*)(bj + c0);
            bc4.x *= wj; bc4.y *= wj; bc4.z *= wj; bc4.w *= wj;
#pragma unroll
            for (int i = 0; i < 8; i++) {
                acc[i][0] += br[i] * bc4.x;
                acc[i][1] += br[i] * bc4.y;
                acc[i][2] += br[i] * bc4.z;
                acc[i][3] += br[i] * bc4.w;
            }
        }
        float* Pm = g_P + (size_t)m * DDIM * DDIM;
#pragma unroll
        for (int i = 0; i < 8; i++)
            *(float4*)(Pm + (r0 + i) * 128 + c0) =
                make_float4(acc[i][0], acc[i][1], acc[i][2], acc[i][3]);
    }
}

// ---------------------------------------------------------------------------
// Kernel 3: out = X @ P  (fp32). grid (32, NMAT), 256 threads, 64-row tiles.
// ---------------------------------------------------------------------------
__global__ __launch_bounds__(256) void recon_kernel(const float* __restrict__ X,
                                                    float* __restrict__ out)
{
    extern __shared__ float sm[];
    float* Ps = sm;          // 128*128
    float* Xs = sm + 16384;  // 64*128
    const int m  = blockIdx.y;
    const int s0 = blockIdx.x * 64;
    const int tid = threadIdx.x;

    const float* Pm = g_P + (size_t)m * DDIM * DDIM;
#pragma unroll
    for (int k = 0; k < 16; k++) {
        int i4 = tid + k * 256;
        *(float4*)(Ps + i4 * 4) = *(const float4*)(Pm + i4 * 4);
    }
    const float* Xm = X + (size_t)m * SLEN * DDIM + (size_t)s0 * DDIM;
#pragma unroll
    for (int k = 0; k < 8; k++) {
        int i4 = tid + k * 256;
        *(float4*)(Xs + i4 * 4) = *(const float4*)(Xm + i4 * 4);
    }
    __syncthreads();

    const int tx = tid & 31, ty = tid >> 5;   // 32 x 8
    const int c0 = tx * 4, r0 = ty * 8;
    float acc[8][4];
#pragma unroll
    for (int i = 0; i < 8; i++)
#pragma unroll
        for (int l = 0; l < 4; l++) acc[i][l] = 0.f;

#pragma unroll 4
    for (int k = 0; k < 128; k++) {
        float4 b4 = *(const float4*)(Ps + k * 128 + c0);
#pragma unroll
        for (int i = 0; i < 8; i++) {
            float a = Xs[(r0 + i) * 128 + k];   // warp-uniform -> broadcast
            acc[i][0] += a * b4.x;
            acc[i][1] += a * b4.y;
            acc[i][2] += a * b4.z;
            acc[i][3] += a * b4.w;
        }
    }

    float* outm = out + (size_t)m * SLEN * DDIM + (size_t)s0 * DDIM;
#pragma unroll
    for (int i = 0; i < 8; i++)
        *(float4*)(outm + (r0 + i) * 128 + c0) =
            make_float4(acc[i][0], acc[i][1], acc[i][2], acc[i][3]);
}

// ---------------------------------------------------------------------------
extern "C" void kernel_launch(void* const* d_in, const int* in_sizes, int n_in,
                              void* d_out, int out_size)
{
    const float* X = (const float*)d_in[0];
    float* out = (float*)d_out;

    cudaFuncSetAttribute(jacobi_kernel, cudaFuncAttributeMaxDynamicSharedMemorySize,
                         128 * 128 * 4);
    cudaFuncSetAttribute(recon_kernel, cudaFuncAttributeMaxDynamicSharedMemorySize,
                         (16384 + 8192) * 4);

    gram_partial_kernel<<<dim3(KCH, NMAT), 256>>>(X);
    jacobi_kernel<<<NMAT, 512, 128 * 128 * 4>>>();
    recon_kernel<<<dim3(SLEN / 64, NMAT), 256, (16384 + 8192) * 4>>>(X, out);
}

// round 4
// speedup vs baseline: 1.6894x; 1.5433x over previous
#include <cuda_runtime.h>
#include <math.h>

#define NMAT   64          // B*H = 4*16 independent matrices
#define SLEN   2048        // rows per matrix
#define DDIM   128         // cols per matrix
#define RANK   64
#define KCH    8           // split-K chunks for Gram
#define SROWS  (SLEN/KCH)  // 256 rows per chunk
#define MAXSWEEPS 7
#define JTH    4e-13f      // rotation skip threshold (g^2 > JTH*a*b)

// scratch (static device globals — no allocations)
__device__ float g_gpart[(size_t)NMAT * KCH * DDIM * DDIM]; // 32 MB Gram partials
__device__ float g_P[(size_t)NMAT * DDIM * DDIM];           // 4 MB projectors

// ---------------------------------------------------------------------------
// Kernel 1: partial Gram  G_m += X_chunk^T X_chunk   (fp32)
// grid (KCH, NMAT), 256 threads, 8x8 register tile per thread
// ---------------------------------------------------------------------------
__global__ __launch_bounds__(256) void gram_partial_kernel(const float* __restrict__ X)
{
    __shared__ float Xs[32 * 128];
    const int m  = blockIdx.y;
    const int kc = blockIdx.x;
    const float* Xm = X + (size_t)m * SLEN * DDIM;
    const int tid = threadIdx.x;
    const int tx = tid & 15, ty = tid >> 4;

    float acc[8][8];
#pragma unroll
    for (int i = 0; i < 8; i++)
#pragma unroll
        for (int j = 0; j < 8; j++) acc[i][j] = 0.f;

    const int s0 = kc * SROWS;
    for (int it = 0; it < SROWS / 32; ++it) {
#pragma unroll
        for (int k = 0; k < 4; k++) {
            int idx = tid + k * 256;            // float4 index within 32x128 tile
            int row = idx >> 5, c4 = idx & 31;
            float4 v = *(const float4*)(Xm + (size_t)(s0 + it * 32 + row) * DDIM + c4 * 4);
            *(float4*)(Xs + row * 128 + c4 * 4) = v;
        }
        __syncthreads();
#pragma unroll
        for (int s = 0; s < 32; s++) {
            float a[8], b[8];
            *(float4*)(a)     = *(const float4*)(Xs + s * 128 + ty * 8);
            *(float4*)(a + 4) = *(const float4*)(Xs + s * 128 + ty * 8 + 4);
            *(float4*)(b)     = *(const float4*)(Xs + s * 128 + tx * 8);
            *(float4*)(b + 4) = *(const float4*)(Xs + s * 128 + tx * 8 + 4);
#pragma unroll
            for (int i = 0; i < 8; i++)
#pragma unroll
                for (int j = 0; j < 8; j++) acc[i][j] += a[i] * b[j];
        }
        __syncthreads();
    }

    float* out = g_gpart + ((size_t)m * KCH + kc) * DDIM * DDIM;
#pragma unroll
    for (int i = 0; i < 8; i++) {
        *(float4*)(out + (ty * 8 + i) * 128 + tx * 8)     =
            make_float4(acc[i][0], acc[i][1], acc[i][2], acc[i][3]);
        *(float4*)(out + (ty * 8 + i) * 128 + tx * 8 + 4) =
            make_float4(acc[i][4], acc[i][5], acc[i][6], acc[i][7]);
    }
}

// ---------------------------------------------------------------------------
// Kernel 2: one-sided Jacobi on G (128x128) per matrix; emits projector P.
// 64 blocks x 512 threads — the R1 configuration (measured fastest per round:
// crossbar-bound at ~0.7us/round). Changes vs R1: 7 sweeps (was 12), rotation
// skip threshold 4e-13 (was 1e-14) with write-back skip, early sweep exit.
// ---------------------------------------------------------------------------
__global__ __launch_bounds__(512) void jacobi_kernel()
{
    extern __shared__ float B[];     // [128 cols][128 rows], col-major
    __shared__ float nrm2[128];
    __shared__ float w[128];
    __shared__ int any_rot;

    const int m   = blockIdx.x;
    const int tid = threadIdx.x;

    // load + reduce split-K partials directly into SMEM (G symmetric, so
    // row-major source == col-major dest)
    const float* gp = g_gpart + (size_t)m * KCH * DDIM * DDIM;
#pragma unroll
    for (int k = 0; k < 8; k++) {
        int i4 = tid + k * 512;
        float4 s = make_float4(0.f, 0.f, 0.f, 0.f);
#pragma unroll
        for (int p = 0; p < KCH; p++) {
            float4 v = *(const float4*)(gp + (size_t)p * DDIM * DDIM + i4 * 4);
            s.x += v.x; s.y += v.y; s.z += v.z; s.w += v.w;
        }
        *(float4*)(B + i4 * 4) = s;
    }
    __syncthreads();

    const int pairIdx = tid >> 3;   // 0..63
    const int sub     = tid & 7;    // 8 threads per pair

    for (int sweep = 0; sweep < MAXSWEEPS; ++sweep) {
        // exact column norms (fixes incremental drift each sweep)
        {
            int col = tid >> 2, part = tid & 3;
            const float* bc = B + col * 128;
            float ss = 0.f;
#pragma unroll
            for (int k = 0; k < 8; k++) {
                float4 v = *(const float4*)(bc + (k * 4 + part) * 4);
                ss += v.x * v.x + v.y * v.y + v.z * v.z + v.w * v.w;
            }
            ss += __shfl_xor_sync(0xffffffffu, ss, 1);
            ss += __shfl_xor_sync(0xffffffffu, ss, 2);
            if (part == 0) nrm2[col] = ss;
            if (tid == 0) any_rot = 0;
        }
        __syncthreads();

        for (int r = 0; r < 127; r++) {
            // round-robin tournament pairing (player 127 fixed)
            int p, q;
            if (pairIdx == 0) { p = 127; q = r; }
            else {
                p = r + pairIdx;        if (p >= 127) p -= 127;
                q = r + 127 - pairIdx;  if (q >= 127) q -= 127;
            }
            float* bp = B + p * 128 + sub * 4;
            float* bq = B + q * 128 + sub * 4;
            float4 p4[4], q4[4];
#pragma unroll
            for (int k = 0; k < 4; k++) {
                p4[k] = *(const float4*)(bp + k * 32);
                q4[k] = *(const float4*)(bq + k * 32);
            }
            float g = 0.f;
#pragma unroll
            for (int k = 0; k < 4; k++)
                g += p4[k].x * q4[k].x + p4[k].y * q4[k].y +
                     p4[k].z * q4[k].z + p4[k].w * q4[k].w;
            g += __shfl_xor_sync(0xffffffffu, g, 1);
            g += __shfl_xor_sync(0xffffffffu, g, 2);
            g += __shfl_xor_sync(0xffffffffu, g, 4);

            float al = nrm2[p], be = nrm2[q];
            if (g * g > JTH * al * be) {   // uniform within the 8-lane group
                float zeta = (be - al) / (2.f * g);
                float t = 1.f / (fabsf(zeta) + sqrtf(1.f + zeta * zeta));
                t = (zeta < 0.f) ? -t : t;
                float c  = rsqrtf(1.f + t * t);
                float sn = c * t;
#pragma unroll
                for (int k = 0; k < 4; k++) {
                    float4 np, nq;
                    np.x = c * p4[k].x - sn * q4[k].x;  nq.x = sn * p4[k].x + c * q4[k].x;
                    np.y = c * p4[k].y - sn * q4[k].y;  nq.y = sn * p4[k].y + c * q4[k].y;
                    np.z = c * p4[k].z - sn * q4[k].z;  nq.z = sn * p4[k].z + c * q4[k].z;
                    np.w = c * p4[k].w - sn * q4[k].w;  nq.w = sn * p4[k].w + c * q4[k].w;
                    *(float4*)(bp + k * 32) = np;
                    *(float4*)(bq + k * 32) = nq;
                }
                if (sub == 0) {
                    nrm2[p] = al - t * g;
                    nrm2[q] = be + t * g;
                    any_rot = 1;          // benign same-value race
                }
            }
            __syncthreads();
        }

        // early exit: last round's barrier makes any_rot coherent here.
        int rot = any_rot;
        __syncthreads();          // protect against next sweep's reset racing
        if (!rot) break;
    }

    // final exact norms (||b_k||^2 = lambda_k^2)
    {
        int col = tid >> 2, part = tid & 3;
        const float* bc = B + col * 128;
        float ss = 0.f;
#pragma unroll
        for (int k = 0; k < 8; k++) {
            float4 v = *(const float4*)(bc + (k * 4 + part) * 4);
            ss += v.x * v.x + v.y * v.y + v.z * v.z + v.w * v.w;
        }
        ss += __shfl_xor_sync(0xffffffffu, ss, 1);
        ss += __shfl_xor_sync(0xffffffffu, ss, 2);
        if (part == 0) nrm2[col] = ss;
    }
    __syncthreads();

    // select top-RANK columns by norm; weight = 1/||b||^2 so P = sum w b b^T
    if (tid < 128) {
        float nj = nrm2[tid];
        int rk = 0;
        for (int i = 0; i < 128; i++) {
            float ni = nrm2[i];
            rk += (ni > nj) || (ni == nj && i < tid);
        }
        w[tid] = (rk < RANK) ? 1.f / nj : 0.f;
    }
    __syncthreads();

    // P[r][c] = sum_j w_j * B[j][r] * B[j][c]
    {
        int tx = tid & 31, ty = tid >> 5;     // 32 x 16 thread grid
        int c0 = tx * 4, r0 = ty * 8;
        float acc[8][4];
#pragma unroll
        for (int i = 0; i < 8; i++)
#pragma unroll
            for (int l = 0; l < 4; l++) acc[i][l] = 0.f;

        for (int j = 0; j < 128; j++) {
            float wj = w[j];
            if (wj == 0.f) continue;          // uniform branch: halves work
            const float* bj = B + j * 128;
            float br[8];
            *(float4*)(br)     = *(const float4*)(bj + r0);
            *(float4*)(br + 4) = *(const float4*)(bj + r0 + 4);
            float4 bc4 = *(const float4*)(bj + c0);
            bc4.x *= wj; bc4.y *= wj; bc4.z *= wj; bc4.w *= wj;
#pragma unroll
            for (int i = 0; i < 8; i++) {
                acc[i][0] += br[i] * bc4.x;
                acc[i][1] += br[i] * bc4.y;
                acc[i][2] += br[i] * bc4.z;
                acc[i][3] += br[i] * bc4.w;
            }
        }
        float* Pm = g_P + (size_t)m * DDIM * DDIM;
#pragma unroll
        for (int i = 0; i < 8; i++)
            *(float4*)(Pm + (r0 + i) * 128 + c0) =
                make_float4(acc[i][0], acc[i][1], acc[i][2], acc[i][3]);
    }
}

// ---------------------------------------------------------------------------
// Kernel 3: out = X @ P  (fp32). grid (32, NMAT), 256 threads, 64-row tiles.
// ---------------------------------------------------------------------------
__global__ __launch_bounds__(256) void recon_kernel(const float* __restrict__ X,
                                                    float* __restrict__ out)
{
    extern __shared__ float sm[];
    float* Ps = sm;          // 128*128
    float* Xs = sm + 16384;  // 64*128
    const int m  = blockIdx.y;
    const int s0 = blockIdx.x * 64;
    const int tid = threadIdx.x;

    const float* Pm = g_P + (size_t)m * DDIM * DDIM;
#pragma unroll
    for (int k = 0; k < 16; k++) {
        int i4 = tid + k * 256;
        *(float4*)(Ps + i4 * 4) = *(const float4*)(Pm + i4 * 4);
    }
    const float* Xm = X + (size_t)m * SLEN * DDIM + (size_t)s0 * DDIM;
#pragma unroll
    for (int k = 0; k < 8; k++) {
        int i4 = tid + k * 256;
        *(float4*)(Xs + i4 * 4) = *(const float4*)(Xm + i4 * 4);
    }
    __syncthreads();

    const int tx = tid & 31, ty = tid >> 5;   // 32 x 8
    const int c0 = tx * 4, r0 = ty * 8;
    float acc[8][4];
#pragma unroll
    for (int i = 0; i < 8; i++)
#pragma unroll
        for (int l = 0; l < 4; l++) acc[i][l] = 0.f;

#pragma unroll 4
    for (int k = 0; k < 128; k++) {
        float4 b4 = *(const float4*)(Ps + k * 128 + c0);
#pragma unroll
        for (int i = 0; i < 8; i++) {
            float a = Xs[(r0 + i) * 128 + k];   // warp-uniform -> broadcast
            acc[i][0] += a * b4.x;
            acc[i][1] += a * b4.y;
            acc[i][2] += a * b4.z;
            acc[i][3] += a * b4.w;
        }
    }

    float* outm = out + (size_t)m * SLEN * DDIM + (size_t)s0 * DDIM;
#pragma unroll
    for (int i = 0; i < 8; i++)
        *(float4*)(outm + (r0 + i) * 128 + c0) =
            make_float4(acc[i][0], acc[i][1], acc[i][2], acc[i][3]);
}

// ---------------------------------------------------------------------------
extern "C" void kernel_launch(void* const* d_in, const int* in_sizes, int n_in,
                              void* d_out, int out_size)
{
    const float* X = (const float*)d_in[0];
    float* out = (float*)d_out;

    cudaFuncSetAttribute(jacobi_kernel, cudaFuncAttributeMaxDynamicSharedMemorySize,
                         128 * 128 * 4);
    cudaFuncSetAttribute(recon_kernel, cudaFuncAttributeMaxDynamicSharedMemorySize,
                         (16384 + 8192) * 4);

    gram_partial_kernel<<<dim3(KCH, NMAT), 256>>>(X);
    jacobi_kernel<<<NMAT, 512, 128 * 128 * 4>>>();
    recon_kernel<<<dim3(SLEN / 64, NMAT), 256, (16384 + 8192) * 4>>>(X, out);
}